// round 2
// baseline (speedup 1.0000x reference)
#include <cuda_runtime.h>
#include <cstddef>

// Problem dims
#define NROWS 32768          // B*S = 8*4096
#define EDIM  1024
#define MSIZE 2048

// ---------------- scratch (static device globals; no allocation) -------------
__device__ float       g_part[8192];
__device__ float       g_scal[8];          // 0: xmax, 1: hmax, 2: wscale_k, 3: wscale_o
__device__ signed char g_qx [(size_t)NROWS * EDIM];      // reused for qh
__device__ signed char g_qwk[(size_t)EDIM * EDIM];
__device__ signed char g_qwo[(size_t)EDIM * EDIM];
__device__ float       g_qk [(size_t)NROWS * EDIM];      // query_keys
__device__ float       g_sim[(size_t)NROWS * MSIZE];     // similarities / attn (in-place)
__device__ float       g_h  [(size_t)NROWS * EDIM];      // x + retrieved

// ---------------- reductions -------------------------------------------------
__global__ void absmax_part(const float* __restrict__ x, size_t n4, float* __restrict__ part) {
    const float4* x4 = (const float4*)x;
    float m = 0.f;
    for (size_t i = (size_t)blockIdx.x * blockDim.x + threadIdx.x; i < n4;
         i += (size_t)gridDim.x * blockDim.x) {
        float4 v = x4[i];
        m = fmaxf(m, fmaxf(fmaxf(fabsf(v.x), fabsf(v.y)), fmaxf(fabsf(v.z), fabsf(v.w))));
    }
    __shared__ float red[256];
    red[threadIdx.x] = m; __syncthreads();
    for (int s = 128; s > 0; s >>= 1) {
        if (threadIdx.x < s) red[threadIdx.x] = fmaxf(red[threadIdx.x], red[threadIdx.x + s]);
        __syncthreads();
    }
    if (threadIdx.x == 0) part[blockIdx.x] = red[0];
}

__global__ void abssum_part(const float* __restrict__ x, size_t n4, float* __restrict__ part) {
    const float4* x4 = (const float4*)x;
    float s = 0.f;
    for (size_t i = (size_t)blockIdx.x * blockDim.x + threadIdx.x; i < n4;
         i += (size_t)gridDim.x * blockDim.x) {
        float4 v = x4[i];
        s += fabsf(v.x) + fabsf(v.y) + fabsf(v.z) + fabsf(v.w);
    }
    __shared__ float red[256];
    red[threadIdx.x] = s; __syncthreads();
    for (int st = 128; st > 0; st >>= 1) {
        if (threadIdx.x < st) red[threadIdx.x] += red[threadIdx.x + st];
        __syncthreads();
    }
    if (threadIdx.x == 0) part[blockIdx.x] = red[0];
}

__global__ void finalize_max(const float* __restrict__ part, int npart, float* __restrict__ out) {
    float m = 0.f;
    for (int i = threadIdx.x; i < npart; i += 256) m = fmaxf(m, part[i]);
    __shared__ float red[256];
    red[threadIdx.x] = m; __syncthreads();
    for (int s = 128; s > 0; s >>= 1) {
        if (threadIdx.x < s) red[threadIdx.x] = fmaxf(red[threadIdx.x], red[threadIdx.x + s]);
        __syncthreads();
    }
    if (threadIdx.x == 0) out[0] = red[0];
}

__global__ void finalize_mean(const float* __restrict__ part, int npart, float* __restrict__ out, float n) {
    float s = 0.f;
    for (int i = threadIdx.x; i < npart; i += 256) s += part[i];
    __shared__ float red[256];
    red[threadIdx.x] = s; __syncthreads();
    for (int st = 128; st > 0; st >>= 1) {
        if (threadIdx.x < st) red[threadIdx.x] += red[threadIdx.x + st];
        __syncthreads();
    }
    if (threadIdx.x == 0) out[0] = __fdiv_rn(red[0], n);
}

// ---------------- quantization ----------------------------------------------
__global__ void quantize_act(const float* __restrict__ x, signed char* __restrict__ q,
                             const float* __restrict__ amax, size_t n4) {
    size_t i = (size_t)blockIdx.x * blockDim.x + threadIdx.x;
    if (i >= n4) return;
    float iscale = __fdiv_rn(amax[0], 127.0f);
    float4 v = ((const float4*)x)[i];
    char4 o;
    float r;
    r = rintf(__fdiv_rn(v.x, iscale)); r = fminf(fmaxf(r, -128.f), 127.f); o.x = (signed char)r;
    r = rintf(__fdiv_rn(v.y, iscale)); r = fminf(fmaxf(r, -128.f), 127.f); o.y = (signed char)r;
    r = rintf(__fdiv_rn(v.z, iscale)); r = fminf(fmaxf(r, -128.f), 127.f); o.z = (signed char)r;
    r = rintf(__fdiv_rn(v.w, iscale)); r = fminf(fmaxf(r, -128.f), 127.f); o.w = (signed char)r;
    ((char4*)q)[i] = o;
}

__global__ void quantize_w(const float* __restrict__ W, signed char* __restrict__ q,
                           const float* __restrict__ wscale, size_t n4) {
    size_t i = (size_t)blockIdx.x * blockDim.x + threadIdx.x;
    if (i >= n4) return;
    float thr = 0.5f * wscale[0];
    float4 v = ((const float4*)W)[i];
    char4 o;
    o.x = (fabsf(v.x) > thr) ? (v.x > 0.f ? 1 : -1) : 0;
    o.y = (fabsf(v.y) > thr) ? (v.y > 0.f ? 1 : -1) : 0;
    o.z = (fabsf(v.z) > thr) ? (v.z > 0.f ? 1 : -1) : 0;
    o.w = (fabsf(v.w) > thr) ? (v.w > 0.f ? 1 : -1) : 0;
    ((char4*)q)[i] = o;
}

// ---------------- int8 GEMM (dp4a): C[N,M] = A[N,K] * B[M,K]^T * s + bias ----
__global__ __launch_bounds__(256)
void igemm_nt(const signed char* __restrict__ A8, const signed char* __restrict__ B8,
              const float* __restrict__ bias,
              const float* __restrict__ wscale, const float* __restrict__ amax,
              float* __restrict__ C, int N, int M, int K) {
    const int Ki = K >> 2;                 // packed ints per row
    __shared__ int As[8][132];
    __shared__ int Bs[8][132];
    const int bm = blockIdx.y * 128;
    const int bn = blockIdx.x * 128;
    const int tid = threadIdx.x;
    const int tx = tid & 15, ty = tid >> 4;
    const int lr = tid >> 1;
    const int lk = (tid & 1) * 4;
    const int* Ap = (const int*)A8 + (size_t)(bm + lr) * Ki + lk;
    const int* Bp = (const int*)B8 + (size_t)(bn + lr) * Ki + lk;
    int acc[8][8] = {};
    for (int k0 = 0; k0 < Ki; k0 += 8) {
        int4 a4 = *(const int4*)(Ap + k0);
        int4 b4 = *(const int4*)(Bp + k0);
        As[lk + 0][lr] = a4.x; As[lk + 1][lr] = a4.y; As[lk + 2][lr] = a4.z; As[lk + 3][lr] = a4.w;
        Bs[lk + 0][lr] = b4.x; Bs[lk + 1][lr] = b4.y; Bs[lk + 2][lr] = b4.z; Bs[lk + 3][lr] = b4.w;
        __syncthreads();
#pragma unroll
        for (int k = 0; k < 8; k++) {
            int4 a0 = *(const int4*)&As[k][ty * 8];
            int4 a1 = *(const int4*)&As[k][ty * 8 + 4];
            int4 b0 = *(const int4*)&Bs[k][tx * 8];
            int4 b1 = *(const int4*)&Bs[k][tx * 8 + 4];
            int a[8] = {a0.x, a0.y, a0.z, a0.w, a1.x, a1.y, a1.z, a1.w};
            int b[8] = {b0.x, b0.y, b0.z, b0.w, b1.x, b1.y, b1.z, b1.w};
#pragma unroll
            for (int i = 0; i < 8; i++)
#pragma unroll
                for (int j = 0; j < 8; j++)
                    acc[i][j] = __dp4a(a[i], b[j], acc[i][j]);
        }
        __syncthreads();
    }
    const float scale = wscale[0] * __fdiv_rn(amax[0], 127.0f);
#pragma unroll
    for (int i = 0; i < 8; i++) {
        size_t row = (size_t)(bm + ty * 8 + i);
        float* Crow = C + row * M + bn + tx * 8;
        const float* brow = bias + bn + tx * 8;
#pragma unroll
        for (int j = 0; j < 8; j++) Crow[j] = (float)acc[i][j] * scale + brow[j];
    }
}

// ---------------- fp32 GEMM NT: C[N,M] = alpha * A[N,K] * B[M,K]^T -----------
__global__ __launch_bounds__(256)
void sgemm_nt(const float* __restrict__ A, const float* __restrict__ B,
              float* __restrict__ C, int N, int M, int K, float alpha) {
    __shared__ float As[8][132];
    __shared__ float Bs[8][132];
    const int bm = blockIdx.y * 128;
    const int bn = blockIdx.x * 128;
    const int tid = threadIdx.x;
    const int tx = tid & 15, ty = tid >> 4;
    const int lr = tid >> 1;
    const int lk = (tid & 1) * 4;
    const float* Ap = A + (size_t)(bm + lr) * K + lk;
    const float* Bp = B + (size_t)(bn + lr) * K + lk;
    float acc[8][8] = {};
    for (int k0 = 0; k0 < K; k0 += 8) {
        float4 a4 = *(const float4*)(Ap + k0);
        float4 b4 = *(const float4*)(Bp + k0);
        As[lk + 0][lr] = a4.x; As[lk + 1][lr] = a4.y; As[lk + 2][lr] = a4.z; As[lk + 3][lr] = a4.w;
        Bs[lk + 0][lr] = b4.x; Bs[lk + 1][lr] = b4.y; Bs[lk + 2][lr] = b4.z; Bs[lk + 3][lr] = b4.w;
        __syncthreads();
#pragma unroll
        for (int k = 0; k < 8; k++) {
            float4 a0 = *(const float4*)&As[k][ty * 8];
            float4 a1 = *(const float4*)&As[k][ty * 8 + 4];
            float4 b0 = *(const float4*)&Bs[k][tx * 8];
            float4 b1 = *(const float4*)&Bs[k][tx * 8 + 4];
            float a[8] = {a0.x, a0.y, a0.z, a0.w, a1.x, a1.y, a1.z, a1.w};
            float b[8] = {b0.x, b0.y, b0.z, b0.w, b1.x, b1.y, b1.z, b1.w};
#pragma unroll
            for (int i = 0; i < 8; i++)
#pragma unroll
                for (int j = 0; j < 8; j++)
                    acc[i][j] += a[i] * b[j];
        }
        __syncthreads();
    }
#pragma unroll
    for (int i = 0; i < 8; i++) {
        size_t row = (size_t)(bm + ty * 8 + i);
        float* Crow = C + row * M + bn + tx * 8;
#pragma unroll
        for (int j = 0; j < 8; j++) Crow[j] = acc[i][j] * alpha;
    }
}

// ------------- fp32 GEMM NN + residual: C = A[N,K]*B[K,M] + X ----------------
__global__ __launch_bounds__(256)
void sgemm_nn_add(const float* __restrict__ A, const float* __restrict__ B,
                  const float* __restrict__ X, float* __restrict__ C,
                  int N, int M, int K) {
    __shared__ float As[8][132];
    __shared__ float Bs[8][132];
    const int bm = blockIdx.y * 128;
    const int bn = blockIdx.x * 128;
    const int tid = threadIdx.x;
    const int tx = tid & 15, ty = tid >> 4;
    const int lr = tid >> 1;
    const int lk = (tid & 1) * 4;
    const int lkb = tid >> 5;              // 0..7 (k row of B tile)
    const int lcb = (tid & 31) * 4;        // col in B tile
    const float* Ap = A + (size_t)(bm + lr) * K + lk;
    const float* Bp = B + (size_t)lkb * M + bn + lcb;
    float acc[8][8] = {};
    for (int k0 = 0; k0 < K; k0 += 8) {
        float4 a4 = *(const float4*)(Ap + k0);
        float4 b4 = *(const float4*)(Bp + (size_t)k0 * M);
        As[lk + 0][lr] = a4.x; As[lk + 1][lr] = a4.y; As[lk + 2][lr] = a4.z; As[lk + 3][lr] = a4.w;
        *(float4*)&Bs[lkb][lcb] = b4;
        __syncthreads();
#pragma unroll
        for (int k = 0; k < 8; k++) {
            float4 a0 = *(const float4*)&As[k][ty * 8];
            float4 a1 = *(const float4*)&As[k][ty * 8 + 4];
            float4 b0 = *(const float4*)&Bs[k][tx * 8];
            float4 b1 = *(const float4*)&Bs[k][tx * 8 + 4];
            float a[8] = {a0.x, a0.y, a0.z, a0.w, a1.x, a1.y, a1.z, a1.w};
            float b[8] = {b0.x, b0.y, b0.z, b0.w, b1.x, b1.y, b1.z, b1.w};
#pragma unroll
            for (int i = 0; i < 8; i++)
#pragma unroll
                for (int j = 0; j < 8; j++)
                    acc[i][j] += a[i] * b[j];
        }
        __syncthreads();
    }
#pragma unroll
    for (int i = 0; i < 8; i++) {
        size_t row = (size_t)(bm + ty * 8 + i);
        float* Crow = C + row * M + bn + tx * 8;
        const float* Xrow = X + row * M + bn + tx * 8;
#pragma unroll
        for (int j = 0; j < 8; j++) Crow[j] = acc[i][j] + Xrow[j];
    }
}

// ---------------- row softmax over MSIZE cols --------------------------------
__global__ void softmax_rows(float* __restrict__ S) {
    const size_t row = blockIdx.x;
    float* p = S + row * (size_t)MSIZE;
    const int tid = threadIdx.x;
    float v[8];
#pragma unroll
    for (int i = 0; i < 8; i++) v[i] = p[tid + i * 256];
    float m = v[0];
#pragma unroll
    for (int i = 1; i < 8; i++) m = fmaxf(m, v[i]);
    __shared__ float red[256];
    red[tid] = m; __syncthreads();
    for (int s = 128; s > 0; s >>= 1) {
        if (tid < s) red[tid] = fmaxf(red[tid], red[tid + s]);
        __syncthreads();
    }
    const float rowmax = red[0];
    __syncthreads();
    float sum = 0.f;
#pragma unroll
    for (int i = 0; i < 8; i++) { v[i] = expf(v[i] - rowmax); sum += v[i]; }
    red[tid] = sum; __syncthreads();
    for (int s = 128; s > 0; s >>= 1) {
        if (tid < s) red[tid] += red[tid + s];
        __syncthreads();
    }
    const float inv = __fdiv_rn(1.0f, red[0]);
#pragma unroll
    for (int i = 0; i < 8; i++) p[tid + i * 256] = v[i] * inv;
}

// ---------------- launch -----------------------------------------------------
extern "C" void kernel_launch(void* const* d_in, const int* in_sizes, int n_in,
                              void* d_out, int out_size) {
    const float* x  = (const float*)d_in[0];
    const float* mk = (const float*)d_in[1];
    const float* mv = (const float*)d_in[2];
    const float* Wk = (const float*)d_in[3];
    const float* bk = (const float*)d_in[4];
    // d_in[5], d_in[6] (Wv, bv) are dead: _query_values never reaches the output.
    const float* Wo = (const float*)d_in[7];
    const float* bo = (const float*)d_in[8];
    float* out = (float*)d_out;

    void *pp, *ps, *pqx, *pqwk, *pqwo, *pqk, *psim, *ph;
    cudaGetSymbolAddress(&pp,  g_part);
    cudaGetSymbolAddress(&ps,  g_scal);
    cudaGetSymbolAddress(&pqx, g_qx);
    cudaGetSymbolAddress(&pqwk, g_qwk);
    cudaGetSymbolAddress(&pqwo, g_qwo);
    cudaGetSymbolAddress(&pqk, g_qk);
    cudaGetSymbolAddress(&psim, g_sim);
    cudaGetSymbolAddress(&ph,  g_h);
    float* part = (float*)pp;
    float* scal = (float*)ps;
    signed char* qx  = (signed char*)pqx;
    signed char* qwk = (signed char*)pqwk;
    signed char* qwo = (signed char*)pqwo;
    float* qk  = (float*)pqk;
    float* sim = (float*)psim;
    float* h   = (float*)ph;

    const size_t nx = (size_t)NROWS * EDIM;      // 33.5M
    const size_t nw = (size_t)EDIM * EDIM;       // 1M

    // scales
    absmax_part<<<2048, 256>>>(x, nx / 4, part);
    finalize_max<<<1, 256>>>(part, 2048, scal + 0);
    abssum_part<<<1024, 256>>>(Wk, nw / 4, part + 2048);
    finalize_mean<<<1, 256>>>(part + 2048, 1024, scal + 2, (float)nw);
    abssum_part<<<1024, 256>>>(Wo, nw / 4, part + 6144);
    finalize_mean<<<1, 256>>>(part + 6144, 1024, scal + 3, (float)nw);

    // quantize
    quantize_act<<<(unsigned)(nx / 4 / 256), 256>>>(x, qx, scal + 0, nx / 4);
    quantize_w<<<(unsigned)(nw / 4 / 256), 256>>>(Wk, qwk, scal + 2, nw / 4);
    quantize_w<<<(unsigned)(nw / 4 / 256), 256>>>(Wo, qwo, scal + 3, nw / 4);

    // query_keys = bitnet(x, Wk, bk)
    igemm_nt<<<dim3(EDIM / 128, NROWS / 128), 256>>>(qx, qwk, bk, scal + 2, scal + 0,
                                                     qk, NROWS, EDIM, EDIM);
    // similarities (scaled by 1/sqrt(1024) = 1/32)
    sgemm_nt<<<dim3(MSIZE / 128, NROWS / 128), 256>>>(qk, mk, sim, NROWS, MSIZE, EDIM, 0.03125f);
    // softmax over memory slots
    softmax_rows<<<NROWS, 256>>>(sim);
    // h = x + attn @ memory_values
    sgemm_nn_add<<<dim3(EDIM / 128, NROWS / 128), 256>>>(sim, mv, x, h, NROWS, EDIM, MSIZE);

    // output = bitnet(h, Wo, bo)
    absmax_part<<<2048, 256>>>(h, nx / 4, part + 4096);
    finalize_max<<<1, 256>>>(part + 4096, 2048, scal + 1);
    quantize_act<<<(unsigned)(nx / 4 / 256), 256>>>(h, qx, scal + 1, nx / 4);
    igemm_nt<<<dim3(EDIM / 128, NROWS / 128), 256>>>(qx, qwo, bo, scal + 3, scal + 1,
                                                     out, NROWS, EDIM, EDIM);
}